// round 1
// baseline (speedup 1.0000x reference)
#include <cuda_runtime.h>
#include <math.h>

#define BB 2
#define TT 2048
#define CC 1024
#define HH 16
#define DHD 64
#define NTOK (BB*TT)   // 4096

// Scratch (allocation-free: __device__ globals)
__device__ float g_q[BB*HH*TT*DHD];
__device__ float g_k[BB*HH*TT*DHD];
__device__ float g_v[BB*HH*TT*DHD];
__device__ float g_ao[NTOK*CC];   // attention output, token-major [4096,1024]

// ---------------------------------------------------------------------------
// SGEMM: C[M,N] = A[M,K] @ B[K,N] + bias, 128x128x8 tile, 8x8 per thread.
// MODE 0: A = x, scatter epilogue into g_q/g_k/g_v ([B,H,T,dh] layout)
// MODE 1: A = g_ao, plain epilogue into Out
// ---------------------------------------------------------------------------
template<int MODE>
__global__ __launch_bounds__(256)
void sgemm_kernel(const float* __restrict__ A_in, const float* __restrict__ Bm,
                  const float* __restrict__ bias, float* __restrict__ Out,
                  int M, int N, int K)
{
    __shared__ float As[8][128];
    __shared__ float Bs[8][132];

    const float* A = (MODE == 1) ? (const float*)g_ao : A_in;

    const int row0 = blockIdx.y * 128;
    const int col0 = blockIdx.x * 128;
    const int tid = threadIdx.x;
    const int tx = tid & 15, ty = tid >> 4;

    float acc[8][8];
    #pragma unroll
    for (int i = 0; i < 8; i++)
        #pragma unroll
        for (int j = 0; j < 8; j++) acc[i][j] = 0.f;

    const int arow = tid >> 1;        // 0..127
    const int akc  = (tid & 1) * 4;   // 0 or 4
    const int bk   = tid >> 5;        // 0..7
    const int bcol = (tid & 31) * 4;  // 0..124

    for (int k0 = 0; k0 < K; k0 += 8) {
        float4 a4 = *(const float4*)(A  + (size_t)(row0 + arow) * K + k0 + akc);
        float4 b4 = *(const float4*)(Bm + (size_t)(k0 + bk) * N + col0 + bcol);
        __syncthreads();
        As[akc+0][arow] = a4.x;
        As[akc+1][arow] = a4.y;
        As[akc+2][arow] = a4.z;
        As[akc+3][arow] = a4.w;
        *(float4*)&Bs[bk][bcol] = b4;
        __syncthreads();
        #pragma unroll
        for (int kk = 0; kk < 8; kk++) {
            float4 a0 = *(const float4*)&As[kk][ty*4];
            float4 a1 = *(const float4*)&As[kk][64 + ty*4];
            float4 b0 = *(const float4*)&Bs[kk][tx*4];
            float4 b1 = *(const float4*)&Bs[kk][64 + tx*4];
            float ar[8] = {a0.x,a0.y,a0.z,a0.w,a1.x,a1.y,a1.z,a1.w};
            float br[8] = {b0.x,b0.y,b0.z,b0.w,b1.x,b1.y,b1.z,b1.w};
            #pragma unroll
            for (int i = 0; i < 8; i++)
                #pragma unroll
                for (int j = 0; j < 8; j++)
                    acc[i][j] += ar[i] * br[j];
        }
    }

    // Epilogue
    #pragma unroll
    for (int ib = 0; ib < 2; ib++) {
        #pragma unroll
        for (int i = 0; i < 4; i++) {
            int m = row0 + ib*64 + ty*4 + i;
            #pragma unroll
            for (int jb = 0; jb < 2; jb++) {
                int n = col0 + jb*64 + tx*4;
                float4 bv = *(const float4*)&bias[n];
                float4 v;
                v.x = acc[ib*4+i][jb*4+0] + bv.x;
                v.y = acc[ib*4+i][jb*4+1] + bv.y;
                v.z = acc[ib*4+i][jb*4+2] + bv.z;
                v.w = acc[ib*4+i][jb*4+3] + bv.w;
                if (MODE == 0) {
                    int b = m >> 11, t = m & 2047;
                    int which = n >> 10;
                    int c = n & 1023;
                    int h = c >> 6, d = c & 63;
                    float* dst = (which == 0) ? g_q : ((which == 1) ? g_k : g_v);
                    *(float4*)&dst[((size_t)(b*HH + h) * TT + t) * DHD + d] = v;
                } else {
                    *(float4*)&Out[(size_t)m * N + n] = v;
                }
            }
        }
    }
}

// ---------------------------------------------------------------------------
// Flash-style causal attention. One CTA per (b*h, 64-row q tile).
// 256 threads as 16x16; each thread owns a 4x4 S/P micro-tile and a 4x4 O tile.
// ---------------------------------------------------------------------------
__global__ __launch_bounds__(256)
void attn_kernel()
{
    extern __shared__ float sm[];
    float* Qs = sm;               // 64 x 68
    float* Ks = Qs + 64*68;       // 64 x 68
    float* Vs = Ks + 64*68;       // 64 x 68
    float* Ps = Vs + 64*68;       // 64 x 68

    const int bh = blockIdx.y;                      // 0..31
    const int qt = (int)gridDim.x - 1 - (int)blockIdx.x;  // big tiles first
    const int q0 = qt * 64;

    const float* Qg = g_q + (size_t)bh * TT * DHD;
    const float* Kg = g_k + (size_t)bh * TT * DHD;
    const float* Vg = g_v + (size_t)bh * TT * DHD;

    const int tid = threadIdx.x;
    const int tx = tid & 15, ty = tid >> 4;

    // load Q tile: 64x64 floats = 1024 float4s
    for (int f = tid; f < 1024; f += 256) {
        int r = f >> 4, c4 = (f & 15) * 4;
        *(float4*)&Qs[r*68 + c4] = *(const float4*)&Qg[(size_t)(q0 + r) * DHD + c4];
    }

    float m_i[4], l_i[4], o[4][4];
    #pragma unroll
    for (int i = 0; i < 4; i++) {
        m_i[i] = -INFINITY; l_i[i] = 0.f;
        #pragma unroll
        for (int j = 0; j < 4; j++) o[i][j] = 0.f;
    }

    const float scale = 0.125f;  // 1/sqrt(64)

    for (int kt = 0; kt <= qt; kt++) {
        const int k0 = kt * 64;
        __syncthreads();   // protect Ks/Vs/Ps from previous iteration
        for (int f = tid; f < 1024; f += 256) {
            int r = f >> 4, c4 = (f & 15) * 4;
            *(float4*)&Ks[r*68 + c4] = *(const float4*)&Kg[(size_t)(k0 + r) * DHD + c4];
            *(float4*)&Vs[r*68 + c4] = *(const float4*)&Vg[(size_t)(k0 + r) * DHD + c4];
        }
        __syncthreads();

        // S = Q K^T
        float s[4][4];
        #pragma unroll
        for (int i = 0; i < 4; i++)
            #pragma unroll
            for (int j = 0; j < 4; j++) s[i][j] = 0.f;

        #pragma unroll
        for (int d0 = 0; d0 < 64; d0 += 4) {
            float4 q4[4], k4[4];
            #pragma unroll
            for (int i = 0; i < 4; i++) q4[i] = *(const float4*)&Qs[(ty*4 + i)*68 + d0];
            #pragma unroll
            for (int j = 0; j < 4; j++) k4[j] = *(const float4*)&Ks[(tx*4 + j)*68 + d0];
            #pragma unroll
            for (int i = 0; i < 4; i++)
                #pragma unroll
                for (int j = 0; j < 4; j++)
                    s[i][j] += q4[i].x*k4[j].x + q4[i].y*k4[j].y
                             + q4[i].z*k4[j].z + q4[i].w*k4[j].w;
        }

        // scale + causal mask (only the diagonal tile needs masking)
        if (kt == qt) {
            #pragma unroll
            for (int i = 0; i < 4; i++) {
                int qr = ty*4 + i;
                #pragma unroll
                for (int j = 0; j < 4; j++) {
                    int kc = tx*4 + j;
                    s[i][j] = (kc > qr) ? -INFINITY : s[i][j] * scale;
                }
            }
        } else {
            #pragma unroll
            for (int i = 0; i < 4; i++)
                #pragma unroll
                for (int j = 0; j < 4; j++) s[i][j] *= scale;
        }

        // online softmax
        #pragma unroll
        for (int i = 0; i < 4; i++) {
            float tmax = fmaxf(fmaxf(s[i][0], s[i][1]), fmaxf(s[i][2], s[i][3]));
            #pragma unroll
            for (int off = 8; off >= 1; off >>= 1)
                tmax = fmaxf(tmax, __shfl_xor_sync(0xffffffffu, tmax, off));
            float m_new = fmaxf(m_i[i], tmax);
            float alpha = __expf(m_i[i] - m_new);
            m_i[i] = m_new;
            float rs = 0.f;
            #pragma unroll
            for (int j = 0; j < 4; j++) {
                s[i][j] = __expf(s[i][j] - m_new);
                rs += s[i][j];
            }
            #pragma unroll
            for (int off = 8; off >= 1; off >>= 1)
                rs += __shfl_xor_sync(0xffffffffu, rs, off);
            l_i[i] = l_i[i] * alpha + rs;
            #pragma unroll
            for (int j = 0; j < 4; j++) o[i][j] *= alpha;
        }

        // write P
        #pragma unroll
        for (int i = 0; i < 4; i++) {
            float4 p4 = make_float4(s[i][0], s[i][1], s[i][2], s[i][3]);
            *(float4*)&Ps[(ty*4 + i)*68 + tx*4] = p4;
        }
        __syncthreads();

        // O += P @ V
        #pragma unroll 8
        for (int kk = 0; kk < 64; kk++) {
            float4 v4 = *(const float4*)&Vs[kk*68 + tx*4];
            float p0 = Ps[(ty*4 + 0)*68 + kk];
            float p1 = Ps[(ty*4 + 1)*68 + kk];
            float p2 = Ps[(ty*4 + 2)*68 + kk];
            float p3 = Ps[(ty*4 + 3)*68 + kk];
            o[0][0] += p0*v4.x; o[0][1] += p0*v4.y; o[0][2] += p0*v4.z; o[0][3] += p0*v4.w;
            o[1][0] += p1*v4.x; o[1][1] += p1*v4.y; o[1][2] += p1*v4.z; o[1][3] += p1*v4.w;
            o[2][0] += p2*v4.x; o[2][1] += p2*v4.y; o[2][2] += p2*v4.z; o[2][3] += p2*v4.w;
            o[3][0] += p3*v4.x; o[3][1] += p3*v4.y; o[3][2] += p3*v4.z; o[3][3] += p3*v4.w;
        }
    }

    // finalize: write to g_ao in token-major [4096,1024], col = h*64 + d
    const int b = bh >> 4, h = bh & 15;
    #pragma unroll
    for (int i = 0; i < 4; i++) {
        float inv = 1.f / l_i[i];
        int q = q0 + ty*4 + i;
        float4 out4 = make_float4(o[i][0]*inv, o[i][1]*inv, o[i][2]*inv, o[i][3]*inv);
        *(float4*)&g_ao[(size_t)(b*TT + q) * CC + h*64 + tx*4] = out4;
    }
}

// ---------------------------------------------------------------------------
extern "C" void kernel_launch(void* const* d_in, const int* in_sizes, int n_in,
                              void* d_out, int out_size)
{
    const float* x      = (const float*)d_in[0];   // [2,2048,1024]
    const float* W_qkv  = (const float*)d_in[1];   // [1024,3072]
    const float* b_qkv  = (const float*)d_in[2];   // [3072]
    const float* W_proj = (const float*)d_in[3];   // [1024,1024]
    const float* b_proj = (const float*)d_in[4];   // [1024]
    float* out = (float*)d_out;                    // [2,2048,1024]

    // 1) QKV GEMM + scatter
    sgemm_kernel<0><<<dim3(3072/128, 4096/128), 256>>>(x, W_qkv, b_qkv, nullptr,
                                                       NTOK, 3*CC, CC);

    // 2) causal flash attention
    const int smem_bytes = 4 * 64 * 68 * (int)sizeof(float);  // 69632
    cudaFuncSetAttribute(attn_kernel, cudaFuncAttributeMaxDynamicSharedMemorySize,
                         smem_bytes);
    attn_kernel<<<dim3(TT/64, BB*HH), 256, smem_bytes>>>();

    // 3) output projection
    sgemm_kernel<1><<<dim3(1024/128, 4096/128), 256>>>(nullptr, W_proj, b_proj, out,
                                                       NTOK, CC, CC);
}

// round 2
// speedup vs baseline: 1.3704x; 1.3704x over previous
#include <cuda_runtime.h>
#include <math.h>
#include <stdint.h>

#define BB 2
#define TT 2048
#define CC 1024
#define HH 16
#define DHD 64
#define NTOK (BB*TT)   // 4096

// Scratch (allocation-free: __device__ globals)
__device__ float g_q[BB*HH*TT*DHD];
__device__ float g_k[BB*HH*TT*DHD];
__device__ float g_v[BB*HH*TT*DHD];
__device__ float g_ao[NTOK*CC];            // attention output, token-major [4096,1024]
__device__ uint32_t g_wqkvT[3*CC*CC];      // W_qkv^T as tf32 bits, [3072][1024]
__device__ uint32_t g_wprojT[CC*CC];       // W_proj^T as tf32 bits, [1024][1024]

// ---------------------------------------------------------------------------
__device__ __forceinline__ uint32_t cvt_tf32(float f) {
    uint32_t u; asm("cvt.rna.tf32.f32 %0, %1;" : "=r"(u) : "f"(f)); return u;
}
__device__ __forceinline__ uint32_t smem_u32(const void* p) {
    return (uint32_t)__cvta_generic_to_shared(p);
}
__device__ __forceinline__ void ldsm4(uint32_t& r0, uint32_t& r1, uint32_t& r2,
                                      uint32_t& r3, uint32_t a) {
    asm volatile("ldmatrix.sync.aligned.m8n8.x4.shared.b16 {%0,%1,%2,%3},[%4];"
                 : "=r"(r0), "=r"(r1), "=r"(r2), "=r"(r3) : "r"(a));
}
__device__ __forceinline__ void mma8(float4& d, const uint32_t* a,
                                     uint32_t b0, uint32_t b1) {
    asm volatile("mma.sync.aligned.m16n8k8.row.col.f32.tf32.tf32.f32 "
                 "{%0,%1,%2,%3},{%4,%5,%6,%7},{%8,%9},{%0,%1,%2,%3};"
                 : "+f"(d.x), "+f"(d.y), "+f"(d.z), "+f"(d.w)
                 : "r"(a[0]), "r"(a[1]), "r"(a[2]), "r"(a[3]), "r"(b0), "r"(b1));
}

// ---------------------------------------------------------------------------
// Transpose + tf32-convert: Wt[n*K + k] = tf32(W[k*N + n])
// ---------------------------------------------------------------------------
__global__ void transpose_cvt(const float* __restrict__ W, uint32_t* __restrict__ Wt,
                              int K, int N)
{
    __shared__ float tile[32][33];
    const int n0 = blockIdx.x * 32, k0 = blockIdx.y * 32;
    const int tx = threadIdx.x, ty = threadIdx.y;
    #pragma unroll
    for (int i = ty; i < 32; i += 8)
        tile[i][tx] = W[(size_t)(k0 + i) * N + n0 + tx];
    __syncthreads();
    #pragma unroll
    for (int i = ty; i < 32; i += 8)
        Wt[(size_t)(n0 + i) * K + k0 + tx] = cvt_tf32(tile[tx][i]);
}

// ---------------------------------------------------------------------------
// tf32 tensor-core GEMM: C[M,N] = A[M,K] @ Bt[N,K]^T + bias
// CTA 128x128, K-tile 16, 8 warps (2x4), warp tile 64x32, double-buffered smem.
// MODE 0: A = x, scatter epilogue into g_q/g_k/g_v ([B,H,T,dh])
// MODE 1: A = g_ao, plain epilogue into Out
// ---------------------------------------------------------------------------
template<int MODE>
__global__ __launch_bounds__(256)
void mma_gemm(const float* __restrict__ A_in, const uint32_t* __restrict__ Bt,
              const float* __restrict__ bias, float* __restrict__ Out,
              int M, int N, int K)
{
    // rows of 16 k-values padded to 20 (conflict-free LDSM across 8-row phases)
    __shared__ __align__(16) uint32_t As[2][128 * 20];
    __shared__ __align__(16) uint32_t Bs[2][128 * 20];

    const float* A = (MODE == 1) ? (const float*)g_ao : A_in;
    const int row0 = blockIdx.y * 128, col0 = blockIdx.x * 128;
    const int tid = threadIdx.x, lane = tid & 31, wid = tid >> 5;
    const int wm = (wid >> 2) * 64, wn = (wid & 3) * 32;
    const int g = lane >> 2, tg = lane & 3;

    float4 c[4][4];
    #pragma unroll
    for (int i = 0; i < 4; i++)
        #pragma unroll
        for (int j = 0; j < 4; j++) c[i][j] = make_float4(0.f, 0.f, 0.f, 0.f);

    const int aRow = tid >> 2;            // 0..63 (second row = +64)
    const int c4   = (tid & 3) * 4;       // k-chunk within 16

    // per-lane LDSM base addresses (tile = lane>>3)
    const uint32_t aBase = smem_u32(&As[0][0]) +
        ((((wm + (lane & 7) + ((lane >> 3) & 1) * 8) * 20) + ((lane >> 4) << 2)) << 2);
    const uint32_t bBase = smem_u32(&Bs[0][0]) +
        ((((wn + ((lane >> 4) << 3) + (lane & 7)) * 20) + (((lane >> 3) & 1) << 2)) << 2);

    const int NKT = K / 16;

    float4 pa0, pa1; uint4 pb0, pb1;
    {   // prologue: tile 0 global -> regs -> smem buf 0
        const float* Ap = A + (size_t)(row0 + aRow) * K + c4;
        pa0 = *(const float4*)Ap;
        pa1 = *(const float4*)(Ap + (size_t)64 * K);
        const uint32_t* Bp = Bt + (size_t)(col0 + aRow) * K + c4;
        pb0 = *(const uint4*)Bp;
        pb1 = *(const uint4*)(Bp + (size_t)64 * K);
        uint4 ua0 = make_uint4(cvt_tf32(pa0.x), cvt_tf32(pa0.y), cvt_tf32(pa0.z), cvt_tf32(pa0.w));
        uint4 ua1 = make_uint4(cvt_tf32(pa1.x), cvt_tf32(pa1.y), cvt_tf32(pa1.z), cvt_tf32(pa1.w));
        *(uint4*)&As[0][aRow * 20 + c4] = ua0;
        *(uint4*)&As[0][(aRow + 64) * 20 + c4] = ua1;
        *(uint4*)&Bs[0][aRow * 20 + c4] = pb0;
        *(uint4*)&Bs[0][(aRow + 64) * 20 + c4] = pb1;
    }
    __syncthreads();

    int buf = 0;
    for (int kt = 0; kt < NKT; kt++) {
        if (kt + 1 < NKT) {   // prefetch next tile to regs
            const float* Ap = A + (size_t)(row0 + aRow) * K + (kt + 1) * 16 + c4;
            pa0 = *(const float4*)Ap;
            pa1 = *(const float4*)(Ap + (size_t)64 * K);
            const uint32_t* Bp = Bt + (size_t)(col0 + aRow) * K + (kt + 1) * 16 + c4;
            pb0 = *(const uint4*)Bp;
            pb1 = *(const uint4*)(Bp + (size_t)64 * K);
        }
        const uint32_t aB = aBase + buf * (128 * 20 * 4);
        const uint32_t bB = bBase + buf * (128 * 20 * 4);
        #pragma unroll
        for (int s = 0; s < 2; s++) {
            uint32_t af[4][4], bf[4][2];
            #pragma unroll
            for (int fm = 0; fm < 4; fm++)
                ldsm4(af[fm][0], af[fm][1], af[fm][2], af[fm][3],
                      aB + fm * (16 * 20 * 4) + s * 32);
            #pragma unroll
            for (int cb = 0; cb < 2; cb++)
                ldsm4(bf[2*cb][0], bf[2*cb][1], bf[2*cb+1][0], bf[2*cb+1][1],
                      bB + cb * (16 * 20 * 4) + s * 32);
            #pragma unroll
            for (int fm = 0; fm < 4; fm++)
                #pragma unroll
                for (int fn = 0; fn < 4; fn++)
                    mma8(c[fm][fn], af[fm], bf[fn][0], bf[fn][1]);
        }
        if (kt + 1 < NKT) {
            const int nb = buf ^ 1;
            uint4 ua0 = make_uint4(cvt_tf32(pa0.x), cvt_tf32(pa0.y), cvt_tf32(pa0.z), cvt_tf32(pa0.w));
            uint4 ua1 = make_uint4(cvt_tf32(pa1.x), cvt_tf32(pa1.y), cvt_tf32(pa1.z), cvt_tf32(pa1.w));
            *(uint4*)&As[nb][aRow * 20 + c4] = ua0;
            *(uint4*)&As[nb][(aRow + 64) * 20 + c4] = ua1;
            *(uint4*)&Bs[nb][aRow * 20 + c4] = pb0;
            *(uint4*)&Bs[nb][(aRow + 64) * 20 + c4] = pb1;
            __syncthreads();
            buf = nb;
        }
    }

    // epilogue: c0/c1 at (m, n/n+1), c2/c3 at (m+8, n/n+1)
    #pragma unroll
    for (int fm = 0; fm < 4; fm++) {
        #pragma unroll
        for (int fn = 0; fn < 4; fn++) {
            const int m0 = row0 + wm + fm * 16 + g;
            const int n  = col0 + wn + fn * 8 + 2 * tg;
            const float b0v = bias[n], b1v = bias[n + 1];
            float2 lo = make_float2(c[fm][fn].x + b0v, c[fm][fn].y + b1v);
            float2 hi = make_float2(c[fm][fn].z + b0v, c[fm][fn].w + b1v);
            if (MODE == 0) {
                const int which = n >> 10, cc = n & 1023, h = cc >> 6, d = cc & 63;
                float* dst = (which == 0) ? g_q : ((which == 1) ? g_k : g_v);
                int b = m0 >> 11, t = m0 & 2047;
                *(float2*)&dst[((size_t)((b * HH + h) * TT + t)) * DHD + d] = lo;
                const int m1 = m0 + 8; b = m1 >> 11; t = m1 & 2047;
                *(float2*)&dst[((size_t)((b * HH + h) * TT + t)) * DHD + d] = hi;
            } else {
                *(float2*)&Out[(size_t)m0 * N + n] = lo;
                *(float2*)&Out[(size_t)(m0 + 8) * N + n] = hi;
            }
        }
    }
}

// ---------------------------------------------------------------------------
// Flash-style causal attention (fp32). One CTA per (b*h, 64-row q tile).
// ---------------------------------------------------------------------------
__global__ __launch_bounds__(256)
void attn_kernel()
{
    extern __shared__ float sm[];
    float* Qs = sm;               // 64 x 68
    float* Ks = Qs + 64*68;
    float* Vs = Ks + 64*68;
    float* Ps = Vs + 64*68;

    const int bh = blockIdx.y;
    const int qt = (int)gridDim.x - 1 - (int)blockIdx.x;  // big tiles first
    const int q0 = qt * 64;

    const float* Qg = g_q + (size_t)bh * TT * DHD;
    const float* Kg = g_k + (size_t)bh * TT * DHD;
    const float* Vg = g_v + (size_t)bh * TT * DHD;

    const int tid = threadIdx.x;
    const int tx = tid & 15, ty = tid >> 4;

    for (int f = tid; f < 1024; f += 256) {
        int r = f >> 4, c4 = (f & 15) * 4;
        *(float4*)&Qs[r*68 + c4] = *(const float4*)&Qg[(size_t)(q0 + r) * DHD + c4];
    }

    float m_i[4], l_i[4], o[4][4];
    #pragma unroll
    for (int i = 0; i < 4; i++) {
        m_i[i] = -INFINITY; l_i[i] = 0.f;
        #pragma unroll
        for (int j = 0; j < 4; j++) o[i][j] = 0.f;
    }

    const float scale = 0.125f;

    for (int kt = 0; kt <= qt; kt++) {
        const int k0 = kt * 64;
        __syncthreads();
        for (int f = tid; f < 1024; f += 256) {
            int r = f >> 4, c4 = (f & 15) * 4;
            *(float4*)&Ks[r*68 + c4] = *(const float4*)&Kg[(size_t)(k0 + r) * DHD + c4];
            *(float4*)&Vs[r*68 + c4] = *(const float4*)&Vg[(size_t)(k0 + r) * DHD + c4];
        }
        __syncthreads();

        float s[4][4];
        #pragma unroll
        for (int i = 0; i < 4; i++)
            #pragma unroll
            for (int j = 0; j < 4; j++) s[i][j] = 0.f;

        #pragma unroll
        for (int d0 = 0; d0 < 64; d0 += 4) {
            float4 q4[4], k4[4];
            #pragma unroll
            for (int i = 0; i < 4; i++) q4[i] = *(const float4*)&Qs[(ty*4 + i)*68 + d0];
            #pragma unroll
            for (int j = 0; j < 4; j++) k4[j] = *(const float4*)&Ks[(tx*4 + j)*68 + d0];
            #pragma unroll
            for (int i = 0; i < 4; i++)
                #pragma unroll
                for (int j = 0; j < 4; j++)
                    s[i][j] += q4[i].x*k4[j].x + q4[i].y*k4[j].y
                             + q4[i].z*k4[j].z + q4[i].w*k4[j].w;
        }

        if (kt == qt) {
            #pragma unroll
            for (int i = 0; i < 4; i++) {
                int qr = ty*4 + i;
                #pragma unroll
                for (int j = 0; j < 4; j++) {
                    int kc = tx*4 + j;
                    s[i][j] = (kc > qr) ? -INFINITY : s[i][j] * scale;
                }
            }
        } else {
            #pragma unroll
            for (int i = 0; i < 4; i++)
                #pragma unroll
                for (int j = 0; j < 4; j++) s[i][j] *= scale;
        }

        #pragma unroll
        for (int i = 0; i < 4; i++) {
            float tmax = fmaxf(fmaxf(s[i][0], s[i][1]), fmaxf(s[i][2], s[i][3]));
            #pragma unroll
            for (int off = 8; off >= 1; off >>= 1)
                tmax = fmaxf(tmax, __shfl_xor_sync(0xffffffffu, tmax, off));
            float m_new = fmaxf(m_i[i], tmax);
            float alpha = __expf(m_i[i] - m_new);
            m_i[i] = m_new;
            float rs = 0.f;
            #pragma unroll
            for (int j = 0; j < 4; j++) {
                s[i][j] = __expf(s[i][j] - m_new);
                rs += s[i][j];
            }
            #pragma unroll
            for (int off = 8; off >= 1; off >>= 1)
                rs += __shfl_xor_sync(0xffffffffu, rs, off);
            l_i[i] = l_i[i] * alpha + rs;
            #pragma unroll
            for (int j = 0; j < 4; j++) o[i][j] *= alpha;
        }

        #pragma unroll
        for (int i = 0; i < 4; i++) {
            float4 p4 = make_float4(s[i][0], s[i][1], s[i][2], s[i][3]);
            *(float4*)&Ps[(ty*4 + i)*68 + tx*4] = p4;
        }
        __syncthreads();

        #pragma unroll 8
        for (int kk = 0; kk < 64; kk++) {
            float4 v4 = *(const float4*)&Vs[kk*68 + tx*4];
            float p0 = Ps[(ty*4 + 0)*68 + kk];
            float p1 = Ps[(ty*4 + 1)*68 + kk];
            float p2 = Ps[(ty*4 + 2)*68 + kk];
            float p3 = Ps[(ty*4 + 3)*68 + kk];
            o[0][0] += p0*v4.x; o[0][1] += p0*v4.y; o[0][2] += p0*v4.z; o[0][3] += p0*v4.w;
            o[1][0] += p1*v4.x; o[1][1] += p1*v4.y; o[1][2] += p1*v4.z; o[1][3] += p1*v4.w;
            o[2][0] += p2*v4.x; o[2][1] += p2*v4.y; o[2][2] += p2*v4.z; o[2][3] += p2*v4.w;
            o[3][0] += p3*v4.x; o[3][1] += p3*v4.y; o[3][2] += p3*v4.z; o[3][3] += p3*v4.w;
        }
    }

    const int b = bh >> 4, h = bh & 15;
    #pragma unroll
    for (int i = 0; i < 4; i++) {
        float inv = 1.f / l_i[i];
        int q = q0 + ty*4 + i;
        float4 out4 = make_float4(o[i][0]*inv, o[i][1]*inv, o[i][2]*inv, o[i][3]*inv);
        *(float4*)&g_ao[(size_t)(b*TT + q) * CC + h*64 + tx*4] = out4;
    }
}

// ---------------------------------------------------------------------------
extern "C" void kernel_launch(void* const* d_in, const int* in_sizes, int n_in,
                              void* d_out, int out_size)
{
    const float* x      = (const float*)d_in[0];   // [2,2048,1024]
    const float* W_qkv  = (const float*)d_in[1];   // [1024,3072]
    const float* b_qkv  = (const float*)d_in[2];   // [3072]
    const float* W_proj = (const float*)d_in[3];   // [1024,1024]
    const float* b_proj = (const float*)d_in[4];   // [1024]
    float* out = (float*)d_out;                    // [2,2048,1024]

    uint32_t* wqkvT;  cudaGetSymbolAddress((void**)&wqkvT,  g_wqkvT);
    uint32_t* wprojT; cudaGetSymbolAddress((void**)&wprojT, g_wprojT);

    // 0) transpose + tf32-convert weights
    transpose_cvt<<<dim3(3*CC/32, CC/32), dim3(32, 8)>>>(W_qkv,  wqkvT,  CC, 3*CC);
    transpose_cvt<<<dim3(CC/32,   CC/32), dim3(32, 8)>>>(W_proj, wprojT, CC, CC);

    // 1) QKV GEMM (tf32 tensor cores) + scatter
    mma_gemm<0><<<dim3(3*CC/128, NTOK/128), 256>>>(x, wqkvT, b_qkv, nullptr,
                                                   NTOK, 3*CC, CC);

    // 2) causal flash attention
    const int smem_bytes = 4 * 64 * 68 * (int)sizeof(float);  // 69632
    cudaFuncSetAttribute(attn_kernel, cudaFuncAttributeMaxDynamicSharedMemorySize,
                         smem_bytes);
    attn_kernel<<<dim3(TT/64, BB*HH), 256, smem_bytes>>>();

    // 3) output projection (tf32 tensor cores)
    mma_gemm<1><<<dim3(CC/128, NTOK/128), 256>>>(nullptr, wprojT, b_proj, out,
                                                 NTOK, CC, CC);
}

// round 3
// speedup vs baseline: 3.4880x; 2.5453x over previous
#include <cuda_runtime.h>
#include <math.h>
#include <stdint.h>

#define BB 2
#define TT 2048
#define CC 1024
#define HH 16
#define DHD 64
#define NTOK (BB*TT)   // 4096

// Scratch (allocation-free: __device__ globals)
__device__ uint32_t g_q[BB*HH*TT*DHD];    // tf32 bits, [bh][t][d]
__device__ uint32_t g_k[BB*HH*TT*DHD];    // tf32 bits, [bh][t][d]
__device__ uint32_t g_vt[BB*HH*DHD*TT];   // tf32 bits, TRANSPOSED [bh][d][t]
__device__ float    g_ao[NTOK*CC];        // attention out fp32, token-major
__device__ uint32_t g_wqkvT[3*CC*CC];     // W_qkv^T tf32, [3072][1024]
__device__ uint32_t g_wprojT[CC*CC];      // W_proj^T tf32, [1024][1024]

// ---------------------------------------------------------------------------
__device__ __forceinline__ uint32_t cvt_tf32(float f) {
    uint32_t u; asm("cvt.rna.tf32.f32 %0, %1;" : "=r"(u) : "f"(f)); return u;
}
__device__ __forceinline__ uint32_t smem_u32(const void* p) {
    return (uint32_t)__cvta_generic_to_shared(p);
}
__device__ __forceinline__ void ldsm4(uint32_t& r0, uint32_t& r1, uint32_t& r2,
                                      uint32_t& r3, uint32_t a) {
    asm volatile("ldmatrix.sync.aligned.m8n8.x4.shared.b16 {%0,%1,%2,%3},[%4];"
                 : "=r"(r0), "=r"(r1), "=r"(r2), "=r"(r3) : "r"(a));
}
__device__ __forceinline__ void mma8(float4& d, const uint32_t* a,
                                     uint32_t b0, uint32_t b1) {
    asm volatile("mma.sync.aligned.m16n8k8.row.col.f32.tf32.tf32.f32 "
                 "{%0,%1,%2,%3},{%4,%5,%6,%7},{%8,%9},{%0,%1,%2,%3};"
                 : "+f"(d.x), "+f"(d.y), "+f"(d.z), "+f"(d.w)
                 : "r"(a[0]), "r"(a[1]), "r"(a[2]), "r"(a[3]), "r"(b0), "r"(b1));
}

// ---------------------------------------------------------------------------
// Transpose + tf32-convert: Wt[n*K + k] = tf32(W[k*N + n])
// ---------------------------------------------------------------------------
__global__ void transpose_cvt(const float* __restrict__ W, uint32_t* __restrict__ Wt,
                              int K, int N)
{
    __shared__ float tile[32][33];
    const int n0 = blockIdx.x * 32, k0 = blockIdx.y * 32;
    const int tx = threadIdx.x, ty = threadIdx.y;
    #pragma unroll
    for (int i = ty; i < 32; i += 8)
        tile[i][tx] = W[(size_t)(k0 + i) * N + n0 + tx];
    __syncthreads();
    #pragma unroll
    for (int i = ty; i < 32; i += 8)
        Wt[(size_t)(n0 + i) * K + k0 + tx] = cvt_tf32(tile[tx][i]);
}

// ---------------------------------------------------------------------------
// tf32 tensor-core GEMM: C[M,N] = A[M,K] @ Bt[N,K]^T + bias
// MODE 0: A = x, scatter into g_q/g_k (tf32, [bh][t][d]) and g_vt (tf32, [bh][d][t])
// MODE 1: A = g_ao, fp32 epilogue into Out
// ---------------------------------------------------------------------------
template<int MODE>
__global__ __launch_bounds__(256)
void mma_gemm(const float* __restrict__ A_in, const uint32_t* __restrict__ Bt,
              const float* __restrict__ bias, float* __restrict__ Out,
              int M, int N, int K)
{
    __shared__ __align__(16) uint32_t As[2][128 * 20];
    __shared__ __align__(16) uint32_t Bs[2][128 * 20];

    const float* A = (MODE == 1) ? (const float*)g_ao : A_in;
    const int row0 = blockIdx.y * 128, col0 = blockIdx.x * 128;
    const int tid = threadIdx.x, lane = tid & 31, wid = tid >> 5;
    const int wm = (wid >> 2) * 64, wn = (wid & 3) * 32;
    const int g = lane >> 2, tg = lane & 3;

    float4 c[4][4];
    #pragma unroll
    for (int i = 0; i < 4; i++)
        #pragma unroll
        for (int j = 0; j < 4; j++) c[i][j] = make_float4(0.f, 0.f, 0.f, 0.f);

    const int aRow = tid >> 2;
    const int c4   = (tid & 3) * 4;

    const uint32_t aBase = smem_u32(&As[0][0]) +
        ((((wm + (lane & 7) + ((lane >> 3) & 1) * 8) * 20) + ((lane >> 4) << 2)) << 2);
    const uint32_t bBase = smem_u32(&Bs[0][0]) +
        ((((wn + ((lane >> 4) << 3) + (lane & 7)) * 20) + (((lane >> 3) & 1) << 2)) << 2);

    const int NKT = K / 16;

    float4 pa0, pa1; uint4 pb0, pb1;
    {
        const float* Ap = A + (size_t)(row0 + aRow) * K + c4;
        pa0 = *(const float4*)Ap;
        pa1 = *(const float4*)(Ap + (size_t)64 * K);
        const uint32_t* Bp = Bt + (size_t)(col0 + aRow) * K + c4;
        pb0 = *(const uint4*)Bp;
        pb1 = *(const uint4*)(Bp + (size_t)64 * K);
        uint4 ua0 = make_uint4(cvt_tf32(pa0.x), cvt_tf32(pa0.y), cvt_tf32(pa0.z), cvt_tf32(pa0.w));
        uint4 ua1 = make_uint4(cvt_tf32(pa1.x), cvt_tf32(pa1.y), cvt_tf32(pa1.z), cvt_tf32(pa1.w));
        *(uint4*)&As[0][aRow * 20 + c4] = ua0;
        *(uint4*)&As[0][(aRow + 64) * 20 + c4] = ua1;
        *(uint4*)&Bs[0][aRow * 20 + c4] = pb0;
        *(uint4*)&Bs[0][(aRow + 64) * 20 + c4] = pb1;
    }
    __syncthreads();

    int buf = 0;
    for (int kt = 0; kt < NKT; kt++) {
        if (kt + 1 < NKT) {
            const float* Ap = A + (size_t)(row0 + aRow) * K + (kt + 1) * 16 + c4;
            pa0 = *(const float4*)Ap;
            pa1 = *(const float4*)(Ap + (size_t)64 * K);
            const uint32_t* Bp = Bt + (size_t)(col0 + aRow) * K + (kt + 1) * 16 + c4;
            pb0 = *(const uint4*)Bp;
            pb1 = *(const uint4*)(Bp + (size_t)64 * K);
        }
        const uint32_t aB = aBase + buf * (128 * 20 * 4);
        const uint32_t bB = bBase + buf * (128 * 20 * 4);
        #pragma unroll
        for (int s = 0; s < 2; s++) {
            uint32_t af[4][4], bf[4][2];
            #pragma unroll
            for (int fm = 0; fm < 4; fm++)
                ldsm4(af[fm][0], af[fm][1], af[fm][2], af[fm][3],
                      aB + fm * (16 * 20 * 4) + s * 32);
            #pragma unroll
            for (int cb = 0; cb < 2; cb++)
                ldsm4(bf[2*cb][0], bf[2*cb][1], bf[2*cb+1][0], bf[2*cb+1][1],
                      bB + cb * (16 * 20 * 4) + s * 32);
            #pragma unroll
            for (int fm = 0; fm < 4; fm++)
                #pragma unroll
                for (int fn = 0; fn < 4; fn++)
                    mma8(c[fm][fn], af[fm], bf[fn][0], bf[fn][1]);
        }
        if (kt + 1 < NKT) {
            const int nb = buf ^ 1;
            uint4 ua0 = make_uint4(cvt_tf32(pa0.x), cvt_tf32(pa0.y), cvt_tf32(pa0.z), cvt_tf32(pa0.w));
            uint4 ua1 = make_uint4(cvt_tf32(pa1.x), cvt_tf32(pa1.y), cvt_tf32(pa1.z), cvt_tf32(pa1.w));
            *(uint4*)&As[nb][aRow * 20 + c4] = ua0;
            *(uint4*)&As[nb][(aRow + 64) * 20 + c4] = ua1;
            *(uint4*)&Bs[nb][aRow * 20 + c4] = pb0;
            *(uint4*)&Bs[nb][(aRow + 64) * 20 + c4] = pb1;
            __syncthreads();
            buf = nb;
        }
    }

    #pragma unroll
    for (int fm = 0; fm < 4; fm++) {
        #pragma unroll
        for (int fn = 0; fn < 4; fn++) {
            const int m0 = row0 + wm + fm * 16 + g;
            const int m1 = m0 + 8;
            const int n  = col0 + wn + fn * 8 + 2 * tg;
            const float b0v = bias[n], b1v = bias[n + 1];
            float2 lo = make_float2(c[fm][fn].x + b0v, c[fm][fn].y + b1v);
            float2 hi = make_float2(c[fm][fn].z + b0v, c[fm][fn].w + b1v);
            if (MODE == 0) {
                const int which = n >> 10, cc = n & 1023, h = cc >> 6, d = cc & 63;
                const int b = m0 >> 11, t = m0 & 2047;   // same b for m0, m1
                if (which < 2) {
                    uint32_t* dst = (which == 0) ? g_q : g_k;
                    uint2 ulo = make_uint2(cvt_tf32(lo.x), cvt_tf32(lo.y));
                    uint2 uhi = make_uint2(cvt_tf32(hi.x), cvt_tf32(hi.y));
                    *(uint2*)&dst[((size_t)((b * HH + h) * TT + t)) * DHD + d] = ulo;
                    *(uint2*)&dst[((size_t)((b * HH + h) * TT + t + 8)) * DHD + d] = uhi;
                } else {
                    uint32_t* dst = g_vt + (size_t)(b * HH + h) * DHD * TT;
                    dst[(size_t)d * TT + t]           = cvt_tf32(lo.x);
                    dst[(size_t)(d + 1) * TT + t]     = cvt_tf32(lo.y);
                    dst[(size_t)d * TT + t + 8]       = cvt_tf32(hi.x);
                    dst[(size_t)(d + 1) * TT + t + 8] = cvt_tf32(hi.y);
                }
            } else {
                *(float2*)&Out[(size_t)m0 * N + n] = lo;
                *(float2*)&Out[(size_t)m1 * N + n] = hi;
            }
        }
    }
}

// ---------------------------------------------------------------------------
// Tensor-core causal flash attention (tf32 MMA).
// CTA = (bh, 128-row q tile), 8 warps x m16. K-tile = 64 keys.
// ---------------------------------------------------------------------------
__global__ __launch_bounds__(256)
void attn_kernel()
{
    extern __shared__ uint32_t smu[];
    uint32_t* Qs  = smu;              // 128 x 68 (aliased by Ps after Q frags read)
    uint32_t* Ks  = Qs + 128 * 68;    // 64 x 68
    uint32_t* Vts = Ks + 64 * 68;     // 64 x 68  (rows = d, cols = key)
    uint32_t* Ps  = Qs;               // alias: warp-private rows

    const int bh = blockIdx.y;
    const int qt = (int)gridDim.x - 1 - (int)blockIdx.x;  // big tiles first
    const int q0 = qt * 128;
    const int tid = threadIdx.x, lane = tid & 31, wid = tid >> 5;
    const int wm = wid * 16;
    const int g = lane >> 2, tg = lane & 3;

    const uint32_t* Qg = g_q  + (size_t)bh * TT * DHD;
    const uint32_t* Kg = g_k  + (size_t)bh * TT * DHD;
    const uint32_t* Vg = g_vt + (size_t)bh * DHD * TT;

    // load Q tile 128x64
    #pragma unroll
    for (int i = 0; i < 8; i++) {
        int idx = tid + i * 256; int r = idx >> 4, c4 = (idx & 15) * 4;
        *(uint4*)&Qs[r * 68 + c4] = *(const uint4*)&Qg[(size_t)(q0 + r) * DHD + c4];
    }
    __syncthreads();

    // preload Q fragments (m16 x k64 per warp)
    uint32_t qf[8][4];
    const uint32_t aQ = smem_u32(Qs) +
        ((((wm + (lane & 7) + ((lane >> 3) & 1) * 8) * 68) + ((lane >> 4) << 2)) << 2);
    #pragma unroll
    for (int kc = 0; kc < 8; kc++)
        ldsm4(qf[kc][0], qf[kc][1], qf[kc][2], qf[kc][3], aQ + kc * 32);

    const uint32_t bK = smem_u32(Ks) +
        (((((lane >> 4) << 3) + (lane & 7)) * 68 + (((lane >> 3) & 1) << 2)) << 2);
    const uint32_t bV = smem_u32(Vts) +
        (((((lane >> 4) << 3) + (lane & 7)) * 68 + (((lane >> 3) & 1) << 2)) << 2);
    const uint32_t aP = smem_u32(Ps) +
        ((((wm + (lane & 7) + ((lane >> 3) & 1) * 8) * 68) + ((lane >> 4) << 2)) << 2);

    float4 o[8];
    #pragma unroll
    for (int fn = 0; fn < 8; fn++) o[fn] = make_float4(0.f, 0.f, 0.f, 0.f);
    float m0 = -INFINITY, m1 = -INFINITY, l0 = 0.f, l1 = 0.f;
    const float scale = 0.125f;
    const int r0g = q0 + wm + g, r1g = r0g + 8;
    const int NT = 2 * qt + 2;

    for (int kt = 0; kt < NT; kt++) {
        const int k0 = kt * 64;
        __syncthreads();
        #pragma unroll
        for (int i = 0; i < 4; i++) {
            int idx = tid + i * 256; int r = idx >> 4, c4 = (idx & 15) * 4;
            *(uint4*)&Ks[r * 68 + c4]  = *(const uint4*)&Kg[(size_t)(k0 + r) * DHD + c4];
            *(uint4*)&Vts[r * 68 + c4] = *(const uint4*)&Vg[(size_t)r * TT + k0 + c4];
        }
        __syncthreads();

        if (k0 > q0 + wm + 15) continue;   // tile fully above diagonal for this warp

        // S = Q K^T  (m16 x n64)
        float4 s[8];
        #pragma unroll
        for (int fn = 0; fn < 8; fn++) s[fn] = make_float4(0.f, 0.f, 0.f, 0.f);
        #pragma unroll
        for (int kc = 0; kc < 8; kc++) {
            #pragma unroll
            for (int cb = 0; cb < 4; cb++) {
                uint32_t b0, b1, b2, b3;
                ldsm4(b0, b1, b2, b3, bK + cb * (16 * 68 * 4) + kc * 32);
                mma8(s[2*cb],   qf[kc], b0, b1);
                mma8(s[2*cb+1], qf[kc], b2, b3);
            }
        }

        // scale + causal mask
        const bool domask = (k0 + 63 > q0 + wm);
        #pragma unroll
        for (int fn = 0; fn < 8; fn++) {
            s[fn].x *= scale; s[fn].y *= scale; s[fn].z *= scale; s[fn].w *= scale;
            if (domask) {
                int c0 = k0 + fn * 8 + 2 * tg, c1 = c0 + 1;
                if (c0 > r0g) s[fn].x = -INFINITY;
                if (c1 > r0g) s[fn].y = -INFINITY;
                if (c0 > r1g) s[fn].z = -INFINITY;
                if (c1 > r1g) s[fn].w = -INFINITY;
            }
        }

        // online softmax (rows g and g+8; quad reduction)
        float rmax0 = -INFINITY, rmax1 = -INFINITY;
        #pragma unroll
        for (int fn = 0; fn < 8; fn++) {
            rmax0 = fmaxf(rmax0, fmaxf(s[fn].x, s[fn].y));
            rmax1 = fmaxf(rmax1, fmaxf(s[fn].z, s[fn].w));
        }
        rmax0 = fmaxf(rmax0, __shfl_xor_sync(0xffffffffu, rmax0, 1));
        rmax0 = fmaxf(rmax0, __shfl_xor_sync(0xffffffffu, rmax0, 2));
        rmax1 = fmaxf(rmax1, __shfl_xor_sync(0xffffffffu, rmax1, 1));
        rmax1 = fmaxf(rmax1, __shfl_xor_sync(0xffffffffu, rmax1, 2));
        const float mn0 = fmaxf(m0, rmax0), mn1 = fmaxf(m1, rmax1);
        const float al0 = __expf(m0 - mn0), al1 = __expf(m1 - mn1);
        m0 = mn0; m1 = mn1;
        float rs0 = 0.f, rs1 = 0.f;
        #pragma unroll
        for (int fn = 0; fn < 8; fn++) {
            s[fn].x = __expf(s[fn].x - mn0);
            s[fn].y = __expf(s[fn].y - mn0);
            s[fn].z = __expf(s[fn].z - mn1);
            s[fn].w = __expf(s[fn].w - mn1);
            rs0 += s[fn].x + s[fn].y;
            rs1 += s[fn].z + s[fn].w;
        }
        rs0 += __shfl_xor_sync(0xffffffffu, rs0, 1);
        rs0 += __shfl_xor_sync(0xffffffffu, rs0, 2);
        rs1 += __shfl_xor_sync(0xffffffffu, rs1, 1);
        rs1 += __shfl_xor_sync(0xffffffffu, rs1, 2);
        l0 = l0 * al0 + rs0;
        l1 = l1 * al1 + rs1;
        #pragma unroll
        for (int fn = 0; fn < 8; fn++) {
            o[fn].x *= al0; o[fn].y *= al0;
            o[fn].z *= al1; o[fn].w *= al1;
        }

        // P -> smem (warp-private rows), tf32
        #pragma unroll
        for (int fn = 0; fn < 8; fn++) {
            uint2 lo = make_uint2(cvt_tf32(s[fn].x), cvt_tf32(s[fn].y));
            uint2 hi = make_uint2(cvt_tf32(s[fn].z), cvt_tf32(s[fn].w));
            *(uint2*)&Ps[(wm + g) * 68 + fn * 8 + 2 * tg] = lo;
            *(uint2*)&Ps[(wm + g + 8) * 68 + fn * 8 + 2 * tg] = hi;
        }
        __syncwarp();

        // O += P @ V  (B operand from transposed V: rows = d, cols = key)
        #pragma unroll
        for (int kc = 0; kc < 8; kc++) {
            uint32_t pf[4];
            ldsm4(pf[0], pf[1], pf[2], pf[3], aP + kc * 32);
            #pragma unroll
            for (int cb = 0; cb < 4; cb++) {
                uint32_t b0, b1, b2, b3;
                ldsm4(b0, b1, b2, b3, bV + cb * (16 * 68 * 4) + kc * 32);
                mma8(o[2*cb],   pf, b0, b1);
                mma8(o[2*cb+1], pf, b2, b3);
            }
        }
    }

    // finalize -> g_ao token-major
    const int b = bh >> 4, h = bh & 15;
    const float inv0 = 1.f / l0, inv1 = 1.f / l1;
    #pragma unroll
    for (int fn = 0; fn < 8; fn++) {
        const int d = fn * 8 + 2 * tg;
        float2 lo = make_float2(o[fn].x * inv0, o[fn].y * inv0);
        float2 hi = make_float2(o[fn].z * inv1, o[fn].w * inv1);
        *(float2*)&g_ao[(size_t)(b * TT + r0g) * CC + h * 64 + d] = lo;
        *(float2*)&g_ao[(size_t)(b * TT + r1g) * CC + h * 64 + d] = hi;
    }
}

// ---------------------------------------------------------------------------
extern "C" void kernel_launch(void* const* d_in, const int* in_sizes, int n_in,
                              void* d_out, int out_size)
{
    const float* x      = (const float*)d_in[0];
    const float* W_qkv  = (const float*)d_in[1];
    const float* b_qkv  = (const float*)d_in[2];
    const float* W_proj = (const float*)d_in[3];
    const float* b_proj = (const float*)d_in[4];
    float* out = (float*)d_out;

    uint32_t* wqkvT;  cudaGetSymbolAddress((void**)&wqkvT,  g_wqkvT);
    uint32_t* wprojT; cudaGetSymbolAddress((void**)&wprojT, g_wprojT);

    transpose_cvt<<<dim3(3*CC/32, CC/32), dim3(32, 8)>>>(W_qkv,  wqkvT,  CC, 3*CC);
    transpose_cvt<<<dim3(CC/32,   CC/32), dim3(32, 8)>>>(W_proj, wprojT, CC, CC);

    mma_gemm<0><<<dim3(3*CC/128, NTOK/128), 256>>>(x, wqkvT, b_qkv, nullptr,
                                                   NTOK, 3*CC, CC);

    const int smem_bytes = (128*68 + 64*68 + 64*68) * (int)sizeof(uint32_t); // 69632
    cudaFuncSetAttribute(attn_kernel, cudaFuncAttributeMaxDynamicSharedMemorySize,
                         smem_bytes);
    attn_kernel<<<dim3(TT/128, BB*HH), 256, smem_bytes>>>();

    mma_gemm<1><<<dim3(CC/128, NTOK/128), 256>>>(nullptr, wprojT, b_proj, out,
                                                 NTOK, CC, CC);
}

// round 4
// speedup vs baseline: 3.5474x; 1.0170x over previous
#include <cuda_runtime.h>
#include <math.h>
#include <stdint.h>

#define BB 2
#define TT 2048
#define CC 1024
#define HH 16
#define DHD 64
#define NTOK (BB*TT)   // 4096

// Scratch (allocation-free: __device__ globals)
__device__ uint32_t g_xt[NTOK*CC];        // x as tf32 bits
__device__ uint32_t g_q[BB*HH*TT*DHD];    // tf32 bits, [bh][t][d]
__device__ uint32_t g_k[BB*HH*TT*DHD];    // tf32 bits, [bh][t][d]
__device__ uint32_t g_vt[BB*HH*DHD*TT];   // tf32 bits, TRANSPOSED [bh][d][t]
__device__ uint32_t g_ao[NTOK*CC];        // attention out, tf32 bits, token-major
__device__ uint32_t g_wqkvT[3*CC*CC];     // W_qkv^T tf32, [3072][1024]
__device__ uint32_t g_wprojT[CC*CC];      // W_proj^T tf32, [1024][1024]

// ---------------------------------------------------------------------------
__device__ __forceinline__ uint32_t cvt_tf32(float f) {
    uint32_t u; asm("cvt.rna.tf32.f32 %0, %1;" : "=r"(u) : "f"(f)); return u;
}
__device__ __forceinline__ uint32_t smem_u32(const void* p) {
    return (uint32_t)__cvta_generic_to_shared(p);
}
__device__ __forceinline__ void ldsm4(uint32_t& r0, uint32_t& r1, uint32_t& r2,
                                      uint32_t& r3, uint32_t a) {
    asm volatile("ldmatrix.sync.aligned.m8n8.x4.shared.b16 {%0,%1,%2,%3},[%4];"
                 : "=r"(r0), "=r"(r1), "=r"(r2), "=r"(r3) : "r"(a));
}
__device__ __forceinline__ void mma8(float4& d, const uint32_t* a,
                                     uint32_t b0, uint32_t b1) {
    asm volatile("mma.sync.aligned.m16n8k8.row.col.f32.tf32.tf32.f32 "
                 "{%0,%1,%2,%3},{%4,%5,%6,%7},{%8,%9},{%0,%1,%2,%3};"
                 : "+f"(d.x), "+f"(d.y), "+f"(d.z), "+f"(d.w)
                 : "r"(a[0]), "r"(a[1]), "r"(a[2]), "r"(a[3]), "r"(b0), "r"(b1));
}
__device__ __forceinline__ void cp16(uint32_t s, const void* g) {
    asm volatile("cp.async.cg.shared.global [%0], [%1], 16;" :: "r"(s), "l"(g));
}
__device__ __forceinline__ void cp_commit() {
    asm volatile("cp.async.commit_group;");
}
template<int N>
__device__ __forceinline__ void cp_wait() {
    asm volatile("cp.async.wait_group %0;" :: "n"(N));
}

// ---------------------------------------------------------------------------
__global__ void cvt_f32_tf32(const float* __restrict__ in, uint32_t* __restrict__ out,
                             int n4)
{
    int i = blockIdx.x * blockDim.x + threadIdx.x;
    if (i < n4) {
        float4 v = ((const float4*)in)[i];
        ((uint4*)out)[i] = make_uint4(cvt_tf32(v.x), cvt_tf32(v.y),
                                      cvt_tf32(v.z), cvt_tf32(v.w));
    }
}

// Transpose + tf32-convert: Wt[n*K + k] = tf32(W[k*N + n])
__global__ void transpose_cvt(const float* __restrict__ W, uint32_t* __restrict__ Wt,
                              int K, int N)
{
    __shared__ float tile[32][33];
    const int n0 = blockIdx.x * 32, k0 = blockIdx.y * 32;
    const int tx = threadIdx.x, ty = threadIdx.y;
    #pragma unroll
    for (int i = ty; i < 32; i += 8)
        tile[i][tx] = W[(size_t)(k0 + i) * N + n0 + tx];
    __syncthreads();
    #pragma unroll
    for (int i = ty; i < 32; i += 8)
        Wt[(size_t)(n0 + i) * K + k0 + tx] = cvt_tf32(tile[tx][i]);
}

// ---------------------------------------------------------------------------
// tf32 tensor-core GEMM with 4-stage cp.async ring.
// C[M,N] = A[M,K](tf32 bits) @ Bt[N,K]^T(tf32 bits) + bias
// MODE 0: scatter into g_q/g_k ([bh][t][d]) and g_vt ([bh][d][t])
// MODE 1: fp32 epilogue into Out
// ---------------------------------------------------------------------------
#define GBUF (128*20)

template<int MODE>
__global__ __launch_bounds__(256)
void mma_gemm(const uint32_t* __restrict__ A, const uint32_t* __restrict__ Bt,
              const float* __restrict__ bias, float* __restrict__ Out,
              int M, int N, int K)
{
    extern __shared__ __align__(16) uint32_t dsm[];
    uint32_t* As = dsm;            // 4 x 128x20
    uint32_t* Bs = dsm + 4 * GBUF; // 4 x 128x20

    const int row0 = blockIdx.y * 128, col0 = blockIdx.x * 128;
    const int tid = threadIdx.x, lane = tid & 31, wid = tid >> 5;
    const int wm = (wid >> 2) * 64, wn = (wid & 3) * 32;
    const int g = lane >> 2, tg = lane & 3;

    float4 c[4][4];
    #pragma unroll
    for (int i = 0; i < 4; i++)
        #pragma unroll
        for (int j = 0; j < 4; j++) c[i][j] = make_float4(0.f, 0.f, 0.f, 0.f);

    const int aRow = tid >> 2;            // 0..63 (+64 second)
    const int c4   = (tid & 3) * 4;

    const uint32_t sA = smem_u32(As), sB = smem_u32(Bs);
    const uint32_t aBase = sA +
        ((((wm + (lane & 7) + ((lane >> 3) & 1) * 8) * 20) + ((lane >> 4) << 2)) << 2);
    const uint32_t bBase = sB +
        ((((wn + ((lane >> 4) << 3) + (lane & 7)) * 20) + (((lane >> 3) & 1) << 2)) << 2);

    const int NKT = K / 16;

    auto issueAB = [&](int kt, int buf) {
        const uint32_t* Ap = A + (size_t)(row0 + aRow) * K + kt * 16 + c4;
        cp16(sA + (buf * GBUF + aRow * 20 + c4) * 4, Ap);
        cp16(sA + (buf * GBUF + (aRow + 64) * 20 + c4) * 4, Ap + (size_t)64 * K);
        const uint32_t* Bp = Bt + (size_t)(col0 + aRow) * K + kt * 16 + c4;
        cp16(sB + (buf * GBUF + aRow * 20 + c4) * 4, Bp);
        cp16(sB + (buf * GBUF + (aRow + 64) * 20 + c4) * 4, Bp + (size_t)64 * K);
        cp_commit();
    };

    issueAB(0, 0); issueAB(1, 1); issueAB(2, 2);

    for (int kt = 0; kt < NKT; kt++) {
        if (kt + 2 < NKT)      cp_wait<2>();
        else if (kt + 1 < NKT) cp_wait<1>();
        else                   cp_wait<0>();
        __syncthreads();
        if (kt + 3 < NKT) issueAB(kt + 3, (kt + 3) & 3);

        const int buf = kt & 3;
        const uint32_t aB = aBase + buf * (GBUF * 4);
        const uint32_t bB = bBase + buf * (GBUF * 4);
        #pragma unroll
        for (int s = 0; s < 2; s++) {
            uint32_t af[4][4], bf[4][2];
            #pragma unroll
            for (int fm = 0; fm < 4; fm++)
                ldsm4(af[fm][0], af[fm][1], af[fm][2], af[fm][3],
                      aB + fm * (16 * 20 * 4) + s * 32);
            #pragma unroll
            for (int cb = 0; cb < 2; cb++)
                ldsm4(bf[2*cb][0], bf[2*cb][1], bf[2*cb+1][0], bf[2*cb+1][1],
                      bB + cb * (16 * 20 * 4) + s * 32);
            #pragma unroll
            for (int fm = 0; fm < 4; fm++)
                #pragma unroll
                for (int fn = 0; fn < 4; fn++)
                    mma8(c[fm][fn], af[fm], bf[fn][0], bf[fn][1]);
        }
    }

    #pragma unroll
    for (int fm = 0; fm < 4; fm++) {
        #pragma unroll
        for (int fn = 0; fn < 4; fn++) {
            const int m0 = row0 + wm + fm * 16 + g;
            const int m1 = m0 + 8;
            const int n  = col0 + wn + fn * 8 + 2 * tg;
            const float b0v = bias[n], b1v = bias[n + 1];
            float2 lo = make_float2(c[fm][fn].x + b0v, c[fm][fn].y + b1v);
            float2 hi = make_float2(c[fm][fn].z + b0v, c[fm][fn].w + b1v);
            if (MODE == 0) {
                const int which = n >> 10, cc = n & 1023, h = cc >> 6, d = cc & 63;
                const int b = m0 >> 11, t = m0 & 2047;
                if (which < 2) {
                    uint32_t* dst = (which == 0) ? g_q : g_k;
                    uint2 ulo = make_uint2(cvt_tf32(lo.x), cvt_tf32(lo.y));
                    uint2 uhi = make_uint2(cvt_tf32(hi.x), cvt_tf32(hi.y));
                    *(uint2*)&dst[((size_t)((b * HH + h) * TT + t)) * DHD + d] = ulo;
                    *(uint2*)&dst[((size_t)((b * HH + h) * TT + t + 8)) * DHD + d] = uhi;
                } else {
                    uint32_t* dst = g_vt + (size_t)(b * HH + h) * DHD * TT;
                    dst[(size_t)d * TT + t]           = cvt_tf32(lo.x);
                    dst[(size_t)(d + 1) * TT + t]     = cvt_tf32(lo.y);
                    dst[(size_t)d * TT + t + 8]       = cvt_tf32(hi.x);
                    dst[(size_t)(d + 1) * TT + t + 8] = cvt_tf32(hi.y);
                }
            } else {
                *(float2*)&Out[(size_t)m0 * N + n] = lo;
                *(float2*)&Out[(size_t)m1 * N + n] = hi;
            }
        }
    }
}

// ---------------------------------------------------------------------------
// Tensor-core causal flash attention, 3-buffer cp.async K/V ring.
// CTA = (bh, 128-row q tile), 8 warps x m16. K-tile = 64 keys.
// ---------------------------------------------------------------------------
#define KVBUF (64*68)

__global__ __launch_bounds__(256)
void attn_kernel()
{
    extern __shared__ __align__(16) uint32_t smu[];
    uint32_t* Qs  = smu;               // 128 x 68 (aliased by Ps)
    uint32_t* Ks  = Qs + 128 * 68;     // 3 x 64 x 68
    uint32_t* Vts = Ks + 3 * KVBUF;    // 3 x 64 x 68 (rows = d, cols = key)
    uint32_t* Ps  = Qs;

    const int bh = blockIdx.y;
    const int qt = (int)gridDim.x - 1 - (int)blockIdx.x;  // big tiles first
    const int q0 = qt * 128;
    const int tid = threadIdx.x, lane = tid & 31, wid = tid >> 5;
    const int wm = wid * 16;
    const int g = lane >> 2, tg = lane & 3;

    const uint32_t* Qg = g_q  + (size_t)bh * TT * DHD;
    const uint32_t* Kg = g_k  + (size_t)bh * TT * DHD;
    const uint32_t* Vg = g_vt + (size_t)bh * DHD * TT;

    const uint32_t sQ = smem_u32(Qs), sK = smem_u32(Ks), sV = smem_u32(Vts);

    auto issueKV = [&](int kt, int buf) {
        const int k0 = kt * 64;
        #pragma unroll
        for (int i = 0; i < 4; i++) {
            int idx = tid + i * 256; int r = idx >> 4, c4 = (idx & 15) * 4;
            cp16(sK + (buf * KVBUF + r * 68 + c4) * 4,
                 Kg + (size_t)(k0 + r) * DHD + c4);
            cp16(sV + (buf * KVBUF + r * 68 + c4) * 4,
                 Vg + (size_t)r * TT + k0 + c4);
        }
        cp_commit();
    };

    const int NT = 2 * qt + 2;

    // prologue: Q + KV0 as group 0, KV1 as group 1
    #pragma unroll
    for (int i = 0; i < 8; i++) {
        int idx = tid + i * 256; int r = idx >> 4, c4 = (idx & 15) * 4;
        cp16(sQ + (r * 68 + c4) * 4, Qg + (size_t)(q0 + r) * DHD + c4);
    }
    {
        const int k0 = 0;
        #pragma unroll
        for (int i = 0; i < 4; i++) {
            int idx = tid + i * 256; int r = idx >> 4, c4 = (idx & 15) * 4;
            cp16(sK + (r * 68 + c4) * 4, Kg + (size_t)(k0 + r) * DHD + c4);
            cp16(sV + (r * 68 + c4) * 4, Vg + (size_t)r * TT + k0 + c4);
        }
        cp_commit();
    }
    issueKV(1, 1);

    // per-lane LDSM bases
    const uint32_t aQ = sQ +
        ((((wm + (lane & 7) + ((lane >> 3) & 1) * 8) * 68) + ((lane >> 4) << 2)) << 2);
    const uint32_t kOff =
        (((((lane >> 4) << 3) + (lane & 7)) * 68 + (((lane >> 3) & 1) << 2)) << 2);
    const uint32_t aP = aQ;   // Ps aliases Qs, same fragment base

    uint32_t qf[8][4];
    float4 o[8];
    #pragma unroll
    for (int fn = 0; fn < 8; fn++) o[fn] = make_float4(0.f, 0.f, 0.f, 0.f);
    float m0 = -INFINITY, m1 = -INFINITY, l0 = 0.f, l1 = 0.f;
    const float scale = 0.125f;
    const int r0g = q0 + wm + g, r1g = r0g + 8;

    for (int kt = 0; kt < NT; kt++) {
        const int k0 = kt * 64;
        if (kt + 1 < NT) cp_wait<1>();
        else             cp_wait<0>();
        __syncthreads();

        if (kt == 0) {
            #pragma unroll
            for (int kc = 0; kc < 8; kc++)
                ldsm4(qf[kc][0], qf[kc][1], qf[kc][2], qf[kc][3], aQ + kc * 32);
        }
        if (kt + 2 < NT) issueKV(kt + 2, (kt + 2) % 3);

        if (k0 > q0 + wm + 15) continue;   // fully above diagonal for this warp

        const int buf = kt % 3;
        const uint32_t bK = sK + buf * (KVBUF * 4) + kOff;
        const uint32_t bV = sV + buf * (KVBUF * 4) + kOff;

        // S = Q K^T  (m16 x n64)
        float4 s[8];
        #pragma unroll
        for (int fn = 0; fn < 8; fn++) s[fn] = make_float4(0.f, 0.f, 0.f, 0.f);
        #pragma unroll
        for (int kc = 0; kc < 8; kc++) {
            #pragma unroll
            for (int cb = 0; cb < 4; cb++) {
                uint32_t b0, b1, b2, b3;
                ldsm4(b0, b1, b2, b3, bK + cb * (16 * 68 * 4) + kc * 32);
                mma8(s[2*cb],   qf[kc], b0, b1);
                mma8(s[2*cb+1], qf[kc], b2, b3);
            }
        }

        const bool domask = (k0 + 63 > q0 + wm);
        #pragma unroll
        for (int fn = 0; fn < 8; fn++) {
            s[fn].x *= scale; s[fn].y *= scale; s[fn].z *= scale; s[fn].w *= scale;
            if (domask) {
                int c0 = k0 + fn * 8 + 2 * tg, c1 = c0 + 1;
                if (c0 > r0g) s[fn].x = -INFINITY;
                if (c1 > r0g) s[fn].y = -INFINITY;
                if (c0 > r1g) s[fn].z = -INFINITY;
                if (c1 > r1g) s[fn].w = -INFINITY;
            }
        }

        // online softmax (rows g, g+8)
        float rmax0 = -INFINITY, rmax1 = -INFINITY;
        #pragma unroll
        for (int fn = 0; fn < 8; fn++) {
            rmax0 = fmaxf(rmax0, fmaxf(s[fn].x, s[fn].y));
            rmax1 = fmaxf(rmax1, fmaxf(s[fn].z, s[fn].w));
        }
        rmax0 = fmaxf(rmax0, __shfl_xor_sync(0xffffffffu, rmax0, 1));
        rmax0 = fmaxf(rmax0, __shfl_xor_sync(0xffffffffu, rmax0, 2));
        rmax1 = fmaxf(rmax1, __shfl_xor_sync(0xffffffffu, rmax1, 1));
        rmax1 = fmaxf(rmax1, __shfl_xor_sync(0xffffffffu, rmax1, 2));
        const float mn0 = fmaxf(m0, rmax0), mn1 = fmaxf(m1, rmax1);
        const float al0 = __expf(m0 - mn0), al1 = __expf(m1 - mn1);
        m0 = mn0; m1 = mn1;
        float rs0 = 0.f, rs1 = 0.f;
        #pragma unroll
        for (int fn = 0; fn < 8; fn++) {
            s[fn].x = __expf(s[fn].x - mn0);
            s[fn].y = __expf(s[fn].y - mn0);
            s[fn].z = __expf(s[fn].z - mn1);
            s[fn].w = __expf(s[fn].w - mn1);
            rs0 += s[fn].x + s[fn].y;
            rs1 += s[fn].z + s[fn].w;
        }
        rs0 += __shfl_xor_sync(0xffffffffu, rs0, 1);
        rs0 += __shfl_xor_sync(0xffffffffu, rs0, 2);
        rs1 += __shfl_xor_sync(0xffffffffu, rs1, 1);
        rs1 += __shfl_xor_sync(0xffffffffu, rs1, 2);
        l0 = l0 * al0 + rs0;
        l1 = l1 * al1 + rs1;
        #pragma unroll
        for (int fn = 0; fn < 8; fn++) {
            o[fn].x *= al0; o[fn].y *= al0;
            o[fn].z *= al1; o[fn].w *= al1;
        }

        // P -> warp-private smem rows (tf32)
        #pragma unroll
        for (int fn = 0; fn < 8; fn++) {
            uint2 lo = make_uint2(cvt_tf32(s[fn].x), cvt_tf32(s[fn].y));
            uint2 hi = make_uint2(cvt_tf32(s[fn].z), cvt_tf32(s[fn].w));
            *(uint2*)&Ps[(wm + g) * 68 + fn * 8 + 2 * tg] = lo;
            *(uint2*)&Ps[(wm + g + 8) * 68 + fn * 8 + 2 * tg] = hi;
        }
        __syncwarp();

        // O += P @ V
        #pragma unroll
        for (int kc = 0; kc < 8; kc++) {
            uint32_t pf[4];
            ldsm4(pf[0], pf[1], pf[2], pf[3], aP + kc * 32);
            #pragma unroll
            for (int cb = 0; cb < 4; cb++) {
                uint32_t b0, b1, b2, b3;
                ldsm4(b0, b1, b2, b3, bV + cb * (16 * 68 * 4) + kc * 32);
                mma8(o[2*cb],   pf, b0, b1);
                mma8(o[2*cb+1], pf, b2, b3);
            }
        }
    }

    // finalize -> g_ao (tf32 bits), token-major
    const int b = bh >> 4, h = bh & 15;
    const float inv0 = 1.f / l0, inv1 = 1.f / l1;
    #pragma unroll
    for (int fn = 0; fn < 8; fn++) {
        const int d = fn * 8 + 2 * tg;
        uint2 lo = make_uint2(cvt_tf32(o[fn].x * inv0), cvt_tf32(o[fn].y * inv0));
        uint2 hi = make_uint2(cvt_tf32(o[fn].z * inv1), cvt_tf32(o[fn].w * inv1));
        *(uint2*)&g_ao[(size_t)(b * TT + r0g) * CC + h * 64 + d] = lo;
        *(uint2*)&g_ao[(size_t)(b * TT + r1g) * CC + h * 64 + d] = hi;
    }
}

// ---------------------------------------------------------------------------
extern "C" void kernel_launch(void* const* d_in, const int* in_sizes, int n_in,
                              void* d_out, int out_size)
{
    const float* x      = (const float*)d_in[0];
    const float* W_qkv  = (const float*)d_in[1];
    const float* b_qkv  = (const float*)d_in[2];
    const float* W_proj = (const float*)d_in[3];
    const float* b_proj = (const float*)d_in[4];
    float* out = (float*)d_out;

    uint32_t* xt;     cudaGetSymbolAddress((void**)&xt,     g_xt);
    uint32_t* wqkvT;  cudaGetSymbolAddress((void**)&wqkvT,  g_wqkvT);
    uint32_t* wprojT; cudaGetSymbolAddress((void**)&wprojT, g_wprojT);
    uint32_t* ao;     cudaGetSymbolAddress((void**)&ao,     g_ao);

    // 0) convert x to tf32; transpose+convert weights
    cvt_f32_tf32<<<(NTOK*CC/4 + 255)/256, 256>>>(x, xt, NTOK*CC/4);
    transpose_cvt<<<dim3(3*CC/32, CC/32), dim3(32, 8)>>>(W_qkv,  wqkvT,  CC, 3*CC);
    transpose_cvt<<<dim3(CC/32,   CC/32), dim3(32, 8)>>>(W_proj, wprojT, CC, CC);

    const int gemm_smem = 8 * GBUF * (int)sizeof(uint32_t);   // 81920
    cudaFuncSetAttribute(mma_gemm<0>, cudaFuncAttributeMaxDynamicSharedMemorySize,
                         gemm_smem);
    cudaFuncSetAttribute(mma_gemm<1>, cudaFuncAttributeMaxDynamicSharedMemorySize,
                         gemm_smem);

    // 1) QKV GEMM + scatter
    mma_gemm<0><<<dim3(3*CC/128, NTOK/128), 256, gemm_smem>>>(xt, wqkvT, b_qkv,
                                                              nullptr, NTOK, 3*CC, CC);

    // 2) causal flash attention
    const int attn_smem = (128*68 + 6*KVBUF) * (int)sizeof(uint32_t);  // 139264
    cudaFuncSetAttribute(attn_kernel, cudaFuncAttributeMaxDynamicSharedMemorySize,
                         attn_smem);
    attn_kernel<<<dim3(TT/128, BB*HH), 256, attn_smem>>>();

    // 3) output projection
    mma_gemm<1><<<dim3(CC/128, NTOK/128), 256, gemm_smem>>>(ao, wprojT, b_proj,
                                                            out, NTOK, CC, CC);
}

// round 5
// speedup vs baseline: 3.9593x; 1.1161x over previous
#include <cuda_runtime.h>
#include <math.h>
#include <stdint.h>

#define BB 2
#define TT 2048
#define CC 1024
#define HH 16
#define DHD 64
#define NTOK (BB*TT)   // 4096

// Scratch (allocation-free: __device__ globals)
__device__ uint32_t g_xt[NTOK*CC];        // x as tf32 bits
__device__ uint32_t g_q[BB*HH*TT*DHD];    // tf32 bits, [bh][t][d]
__device__ uint32_t g_k[BB*HH*TT*DHD];    // tf32 bits, [bh][t][d]
__device__ uint32_t g_vt[BB*HH*DHD*TT];   // tf32 bits, TRANSPOSED [bh][d][t]
__device__ uint32_t g_ao[NTOK*CC];        // attention out, tf32 bits, token-major
__device__ uint32_t g_wqkvT[3*CC*CC];     // W_qkv^T tf32, [3072][1024]
__device__ uint32_t g_wprojT[CC*CC];      // W_proj^T tf32, [1024][1024]

// ---------------------------------------------------------------------------
__device__ __forceinline__ uint32_t cvt_tf32(float f) {
    uint32_t u; asm("cvt.rna.tf32.f32 %0, %1;" : "=r"(u) : "f"(f)); return u;
}
__device__ __forceinline__ uint32_t smem_u32(const void* p) {
    return (uint32_t)__cvta_generic_to_shared(p);
}
__device__ __forceinline__ void ldsm4(uint32_t& r0, uint32_t& r1, uint32_t& r2,
                                      uint32_t& r3, uint32_t a) {
    asm volatile("ldmatrix.sync.aligned.m8n8.x4.shared.b16 {%0,%1,%2,%3},[%4];"
                 : "=r"(r0), "=r"(r1), "=r"(r2), "=r"(r3) : "r"(a));
}
__device__ __forceinline__ void mma8(float4& d, const uint32_t* a,
                                     uint32_t b0, uint32_t b1) {
    asm volatile("mma.sync.aligned.m16n8k8.row.col.f32.tf32.tf32.f32 "
                 "{%0,%1,%2,%3},{%4,%5,%6,%7},{%8,%9},{%0,%1,%2,%3};"
                 : "+f"(d.x), "+f"(d.y), "+f"(d.z), "+f"(d.w)
                 : "r"(a[0]), "r"(a[1]), "r"(a[2]), "r"(a[3]), "r"(b0), "r"(b1));
}
__device__ __forceinline__ void cp16(uint32_t s, const void* g) {
    asm volatile("cp.async.cg.shared.global [%0], [%1], 16;" :: "r"(s), "l"(g));
}
__device__ __forceinline__ void cp_commit() {
    asm volatile("cp.async.commit_group;");
}
template<int N>
__device__ __forceinline__ void cp_wait() {
    asm volatile("cp.async.wait_group %0;" :: "n"(N));
}

// ---------------------------------------------------------------------------
__global__ void cvt_f32_tf32(const float* __restrict__ in, uint32_t* __restrict__ out,
                             int n4)
{
    int i = blockIdx.x * blockDim.x + threadIdx.x;
    if (i < n4) {
        float4 v = ((const float4*)in)[i];
        ((uint4*)out)[i] = make_uint4(cvt_tf32(v.x), cvt_tf32(v.y),
                                      cvt_tf32(v.z), cvt_tf32(v.w));
    }
}

// Transpose + tf32-convert: Wt[n*K + k] = tf32(W[k*N + n])
__global__ void transpose_cvt(const float* __restrict__ W, uint32_t* __restrict__ Wt,
                              int K, int N)
{
    __shared__ float tile[32][33];
    const int n0 = blockIdx.x * 32, k0 = blockIdx.y * 32;
    const int tx = threadIdx.x, ty = threadIdx.y;
    #pragma unroll
    for (int i = ty; i < 32; i += 8)
        tile[i][tx] = W[(size_t)(k0 + i) * N + n0 + tx];
    __syncthreads();
    #pragma unroll
    for (int i = ty; i < 32; i += 8)
        Wt[(size_t)(n0 + i) * K + k0 + tx] = cvt_tf32(tile[tx][i]);
}

// ---------------------------------------------------------------------------
// tf32 tensor-core GEMM, 4-stage cp.async ring, 4 warps of 64x64.
// C[M,N] = A[M,K](tf32 bits) @ Bt[N,K]^T(tf32 bits) + bias
// MODE 0: scatter into g_q/g_k ([bh][t][d]) and g_vt ([bh][d][t])
// MODE 1: fp32 epilogue into Out
// ---------------------------------------------------------------------------
#define GBUF (128*20)

template<int MODE>
__global__ __launch_bounds__(128)
void mma_gemm(const uint32_t* __restrict__ A, const uint32_t* __restrict__ Bt,
              const float* __restrict__ bias, float* __restrict__ Out,
              int M, int N, int K)
{
    extern __shared__ __align__(16) uint32_t dsm[];
    uint32_t* As = dsm;            // 4 x 128x20
    uint32_t* Bs = dsm + 4 * GBUF; // 4 x 128x20

    const int row0 = blockIdx.y * 128, col0 = blockIdx.x * 128;
    const int tid = threadIdx.x, lane = tid & 31, wid = tid >> 5;
    const int wm = (wid >> 1) * 64, wn = (wid & 1) * 64;
    const int g = lane >> 2, tg = lane & 3;

    float4 c[4][8];
    #pragma unroll
    for (int i = 0; i < 4; i++)
        #pragma unroll
        for (int j = 0; j < 8; j++) c[i][j] = make_float4(0.f, 0.f, 0.f, 0.f);

    const int rB = tid >> 2;              // 0..31 (+32,+64,+96)
    const int c4 = (tid & 3) * 4;

    const uint32_t sA = smem_u32(As), sB = smem_u32(Bs);
    const uint32_t aBase = sA +
        ((((wm + (lane & 7) + ((lane >> 3) & 1) * 8) * 20) + ((lane >> 4) << 2)) << 2);
    const uint32_t bBase = sB +
        ((((wn + ((lane >> 4) << 3) + (lane & 7)) * 20) + (((lane >> 3) & 1) << 2)) << 2);

    const int NKT = K / 16;

    auto issueAB = [&](int kt, int buf) {
        #pragma unroll
        for (int rr = 0; rr < 4; rr++) {
            const int r = rB + rr * 32;
            cp16(sA + (buf * GBUF + r * 20 + c4) * 4,
                 A + (size_t)(row0 + r) * K + kt * 16 + c4);
            cp16(sB + (buf * GBUF + r * 20 + c4) * 4,
                 Bt + (size_t)(col0 + r) * K + kt * 16 + c4);
        }
        cp_commit();
    };

    issueAB(0, 0); issueAB(1, 1); issueAB(2, 2);

    for (int kt = 0; kt < NKT; kt++) {
        if (kt + 2 < NKT)      cp_wait<2>();
        else if (kt + 1 < NKT) cp_wait<1>();
        else                   cp_wait<0>();
        __syncthreads();
        if (kt + 3 < NKT) issueAB(kt + 3, (kt + 3) & 3);

        const int buf = kt & 3;
        const uint32_t aB = aBase + buf * (GBUF * 4);
        const uint32_t bB = bBase + buf * (GBUF * 4);
        #pragma unroll
        for (int s = 0; s < 2; s++) {
            uint32_t af[4][4], bf[8][2];
            #pragma unroll
            for (int fm = 0; fm < 4; fm++)
                ldsm4(af[fm][0], af[fm][1], af[fm][2], af[fm][3],
                      aB + fm * (16 * 20 * 4) + s * 32);
            #pragma unroll
            for (int cb = 0; cb < 4; cb++)
                ldsm4(bf[2*cb][0], bf[2*cb][1], bf[2*cb+1][0], bf[2*cb+1][1],
                      bB + cb * (16 * 20 * 4) + s * 32);
            #pragma unroll
            for (int fm = 0; fm < 4; fm++)
                #pragma unroll
                for (int fn = 0; fn < 8; fn++)
                    mma8(c[fm][fn], af[fm], bf[fn][0], bf[fn][1]);
        }
    }

    #pragma unroll
    for (int fm = 0; fm < 4; fm++) {
        #pragma unroll
        for (int fn = 0; fn < 8; fn++) {
            const int m0 = row0 + wm + fm * 16 + g;
            const int m1 = m0 + 8;
            const int n  = col0 + wn + fn * 8 + 2 * tg;
            const float b0v = bias[n], b1v = bias[n + 1];
            float2 lo = make_float2(c[fm][fn].x + b0v, c[fm][fn].y + b1v);
            float2 hi = make_float2(c[fm][fn].z + b0v, c[fm][fn].w + b1v);
            if (MODE == 0) {
                const int which = n >> 10, cc = n & 1023, h = cc >> 6, d = cc & 63;
                const int b = m0 >> 11, t = m0 & 2047;
                if (which < 2) {
                    uint32_t* dst = (which == 0) ? g_q : g_k;
                    uint2 ulo = make_uint2(cvt_tf32(lo.x), cvt_tf32(lo.y));
                    uint2 uhi = make_uint2(cvt_tf32(hi.x), cvt_tf32(hi.y));
                    *(uint2*)&dst[((size_t)((b * HH + h) * TT + t)) * DHD + d] = ulo;
                    *(uint2*)&dst[((size_t)((b * HH + h) * TT + t + 8)) * DHD + d] = uhi;
                } else {
                    uint32_t* dst = g_vt + (size_t)(b * HH + h) * DHD * TT;
                    dst[(size_t)d * TT + t]           = cvt_tf32(lo.x);
                    dst[(size_t)(d + 1) * TT + t]     = cvt_tf32(lo.y);
                    dst[(size_t)d * TT + t + 8]       = cvt_tf32(hi.x);
                    dst[(size_t)(d + 1) * TT + t + 8] = cvt_tf32(hi.y);
                }
            } else {
                *(float2*)&Out[(size_t)m0 * N + n] = lo;
                *(float2*)&Out[(size_t)m1 * N + n] = hi;
            }
        }
    }
}

// ---------------------------------------------------------------------------
// Tensor-core causal flash attention, 2-stage cp.async KV ring, 2 CTAs/SM.
// CTA = (bh, 64-row q tile), 4 warps x m16. K-tile = 64 keys.
// ---------------------------------------------------------------------------
#define KVBUF (64*68)

__global__ __launch_bounds__(128)
void attn_kernel()
{
    extern __shared__ __align__(16) uint32_t smu[];
    uint32_t* Qs  = smu;               // 64 x 68 (aliased by Ps after Q frag read)
    uint32_t* Ks  = Qs + KVBUF;        // 2 x 64 x 68
    uint32_t* Vts = Ks + 2 * KVBUF;    // 2 x 64 x 68 (rows = d, cols = key)
    uint32_t* Ps  = Qs;

    const int bh = blockIdx.y;
    const int qt = (int)gridDim.x - 1 - (int)blockIdx.x;  // big tiles first
    const int q0 = qt * 64;
    const int tid = threadIdx.x, lane = tid & 31, wid = tid >> 5;
    const int wm = wid * 16;
    const int g = lane >> 2, tg = lane & 3;

    const uint32_t* Qg = g_q  + (size_t)bh * TT * DHD;
    const uint32_t* Kg = g_k  + (size_t)bh * TT * DHD;
    const uint32_t* Vg = g_vt + (size_t)bh * DHD * TT;

    const uint32_t sQ = smem_u32(Qs), sK = smem_u32(Ks), sV = smem_u32(Vts);

    auto issueKV = [&](int kt, int buf) {
        const int k0 = kt * 64;
        #pragma unroll
        for (int i = 0; i < 8; i++) {
            int idx = tid + i * 128; int r = idx >> 4, c4 = (idx & 15) * 4;
            cp16(sK + (buf * KVBUF + r * 68 + c4) * 4,
                 Kg + (size_t)(k0 + r) * DHD + c4);
            cp16(sV + (buf * KVBUF + r * 68 + c4) * 4,
                 Vg + (size_t)r * TT + k0 + c4);
        }
        cp_commit();
    };

    const int NT = qt + 1;

    // prologue: Q + KV0 (group 0), KV1 (group 1)
    #pragma unroll
    for (int i = 0; i < 8; i++) {
        int idx = tid + i * 128; int r = idx >> 4, c4 = (idx & 15) * 4;
        cp16(sQ + (r * 68 + c4) * 4, Qg + (size_t)(q0 + r) * DHD + c4);
        cp16(sK + (r * 68 + c4) * 4, Kg + (size_t)r * DHD + c4);
        cp16(sV + (r * 68 + c4) * 4, Vg + (size_t)r * TT + c4);
    }
    cp_commit();
    issueKV(1, 1);   // keys 64..127 always exist (TT=2048)

    const uint32_t aQ = sQ +
        ((((wm + (lane & 7) + ((lane >> 3) & 1) * 8) * 68) + ((lane >> 4) << 2)) << 2);
    const uint32_t kOff =
        (((((lane >> 4) << 3) + (lane & 7)) * 68 + (((lane >> 3) & 1) << 2)) << 2);
    const uint32_t aP = aQ;

    uint32_t qf[8][4];
    float4 o[8];
    #pragma unroll
    for (int fn = 0; fn < 8; fn++) o[fn] = make_float4(0.f, 0.f, 0.f, 0.f);
    float m0 = -INFINITY, m1 = -INFINITY, l0 = 0.f, l1 = 0.f;
    const float scale = 0.125f;
    const int r0g = q0 + wm + g, r1g = r0g + 8;

    for (int kt = 0; kt < NT; kt++) {
        const int k0 = kt * 64;
        if (kt + 1 < NT) cp_wait<1>();
        else             cp_wait<0>();
        __syncthreads();

        if (kt == 0) {
            #pragma unroll
            for (int kc = 0; kc < 8; kc++)
                ldsm4(qf[kc][0], qf[kc][1], qf[kc][2], qf[kc][3], aQ + kc * 32);
        }

        const int buf = kt & 1;
        const uint32_t bK = sK + buf * (KVBUF * 4) + kOff;
        const uint32_t bV = sV + buf * (KVBUF * 4) + kOff;

        // S = Q K^T  (m16 x n64)
        float4 s[8];
        #pragma unroll
        for (int fn = 0; fn < 8; fn++) s[fn] = make_float4(0.f, 0.f, 0.f, 0.f);
        #pragma unroll
        for (int kc = 0; kc < 8; kc++) {
            #pragma unroll
            for (int cb = 0; cb < 4; cb++) {
                uint32_t b0, b1, b2, b3;
                ldsm4(b0, b1, b2, b3, bK + cb * (16 * 68 * 4) + kc * 32);
                mma8(s[2*cb],   qf[kc], b0, b1);
                mma8(s[2*cb+1], qf[kc], b2, b3);
            }
        }

        const bool domask = (kt == qt);   // only the diagonal tile
        #pragma unroll
        for (int fn = 0; fn < 8; fn++) {
            s[fn].x *= scale; s[fn].y *= scale; s[fn].z *= scale; s[fn].w *= scale;
            if (domask) {
                int c0 = k0 + fn * 8 + 2 * tg, c1 = c0 + 1;
                if (c0 > r0g) s[fn].x = -INFINITY;
                if (c1 > r0g) s[fn].y = -INFINITY;
                if (c0 > r1g) s[fn].z = -INFINITY;
                if (c1 > r1g) s[fn].w = -INFINITY;
            }
        }

        // online softmax (rows g, g+8)
        float rmax0 = -INFINITY, rmax1 = -INFINITY;
        #pragma unroll
        for (int fn = 0; fn < 8; fn++) {
            rmax0 = fmaxf(rmax0, fmaxf(s[fn].x, s[fn].y));
            rmax1 = fmaxf(rmax1, fmaxf(s[fn].z, s[fn].w));
        }
        rmax0 = fmaxf(rmax0, __shfl_xor_sync(0xffffffffu, rmax0, 1));
        rmax0 = fmaxf(rmax0, __shfl_xor_sync(0xffffffffu, rmax0, 2));
        rmax1 = fmaxf(rmax1, __shfl_xor_sync(0xffffffffu, rmax1, 1));
        rmax1 = fmaxf(rmax1, __shfl_xor_sync(0xffffffffu, rmax1, 2));
        const float mn0 = fmaxf(m0, rmax0), mn1 = fmaxf(m1, rmax1);
        const float al0 = __expf(m0 - mn0), al1 = __expf(m1 - mn1);
        m0 = mn0; m1 = mn1;
        float rs0 = 0.f, rs1 = 0.f;
        #pragma unroll
        for (int fn = 0; fn < 8; fn++) {
            s[fn].x = __expf(s[fn].x - mn0);
            s[fn].y = __expf(s[fn].y - mn0);
            s[fn].z = __expf(s[fn].z - mn1);
            s[fn].w = __expf(s[fn].w - mn1);
            rs0 += s[fn].x + s[fn].y;
            rs1 += s[fn].z + s[fn].w;
        }
        rs0 += __shfl_xor_sync(0xffffffffu, rs0, 1);
        rs0 += __shfl_xor_sync(0xffffffffu, rs0, 2);
        rs1 += __shfl_xor_sync(0xffffffffu, rs1, 1);
        rs1 += __shfl_xor_sync(0xffffffffu, rs1, 2);
        l0 = l0 * al0 + rs0;
        l1 = l1 * al1 + rs1;
        #pragma unroll
        for (int fn = 0; fn < 8; fn++) {
            o[fn].x *= al0; o[fn].y *= al0;
            o[fn].z *= al1; o[fn].w *= al1;
        }

        // P -> warp-private smem rows (tf32)
        #pragma unroll
        for (int fn = 0; fn < 8; fn++) {
            uint2 lo = make_uint2(cvt_tf32(s[fn].x), cvt_tf32(s[fn].y));
            uint2 hi = make_uint2(cvt_tf32(s[fn].z), cvt_tf32(s[fn].w));
            *(uint2*)&Ps[(wm + g) * 68 + fn * 8 + 2 * tg] = lo;
            *(uint2*)&Ps[(wm + g + 8) * 68 + fn * 8 + 2 * tg] = hi;
        }
        __syncwarp();

        // O += P @ V
        #pragma unroll
        for (int kc = 0; kc < 8; kc++) {
            uint32_t pf[4];
            ldsm4(pf[0], pf[1], pf[2], pf[3], aP + kc * 32);
            #pragma unroll
            for (int cb = 0; cb < 4; cb++) {
                uint32_t b0, b1, b2, b3;
                ldsm4(b0, b1, b2, b3, bV + cb * (16 * 68 * 4) + kc * 32);
                mma8(o[2*cb],   pf, b0, b1);
                mma8(o[2*cb+1], pf, b2, b3);
            }
        }

        // free this buffer for kt+2, then prefetch
        __syncthreads();
        if (kt + 2 < NT) issueKV(kt + 2, buf);
    }

    // finalize -> g_ao (tf32 bits), token-major
    const int b = bh >> 4, h = bh & 15;
    const float inv0 = 1.f / l0, inv1 = 1.f / l1;
    #pragma unroll
    for (int fn = 0; fn < 8; fn++) {
        const int d = fn * 8 + 2 * tg;
        uint2 lo = make_uint2(cvt_tf32(o[fn].x * inv0), cvt_tf32(o[fn].y * inv0));
        uint2 hi = make_uint2(cvt_tf32(o[fn].z * inv1), cvt_tf32(o[fn].w * inv1));
        *(uint2*)&g_ao[(size_t)(b * TT + r0g) * CC + h * 64 + d] = lo;
        *(uint2*)&g_ao[(size_t)(b * TT + r1g) * CC + h * 64 + d] = hi;
    }
}

// ---------------------------------------------------------------------------
extern "C" void kernel_launch(void* const* d_in, const int* in_sizes, int n_in,
                              void* d_out, int out_size)
{
    const float* x      = (const float*)d_in[0];
    const float* W_qkv  = (const float*)d_in[1];
    const float* b_qkv  = (const float*)d_in[2];
    const float* W_proj = (const float*)d_in[3];
    const float* b_proj = (const float*)d_in[4];
    float* out = (float*)d_out;

    uint32_t* xt;     cudaGetSymbolAddress((void**)&xt,     g_xt);
    uint32_t* wqkvT;  cudaGetSymbolAddress((void**)&wqkvT,  g_wqkvT);
    uint32_t* wprojT; cudaGetSymbolAddress((void**)&wprojT, g_wprojT);
    uint32_t* ao;     cudaGetSymbolAddress((void**)&ao,     g_ao);

    // 0) convert x to tf32; transpose+convert weights
    cvt_f32_tf32<<<(NTOK*CC/4 + 255)/256, 256>>>(x, xt, NTOK*CC/4);
    transpose_cvt<<<dim3(3*CC/32, CC/32), dim3(32, 8)>>>(W_qkv,  wqkvT,  CC, 3*CC);
    transpose_cvt<<<dim3(CC/32,   CC/32), dim3(32, 8)>>>(W_proj, wprojT, CC, CC);

    const int gemm_smem = 8 * GBUF * (int)sizeof(uint32_t);   // 81920
    cudaFuncSetAttribute(mma_gemm<0>, cudaFuncAttributeMaxDynamicSharedMemorySize,
                         gemm_smem);
    cudaFuncSetAttribute(mma_gemm<1>, cudaFuncAttributeMaxDynamicSharedMemorySize,
                         gemm_smem);

    // 1) QKV GEMM + scatter
    mma_gemm<0><<<dim3(3*CC/128, NTOK/128), 128, gemm_smem>>>(xt, wqkvT, b_qkv,
                                                              nullptr, NTOK, 3*CC, CC);

    // 2) causal flash attention (64-row q tiles, 2 CTAs/SM)
    const int attn_smem = 5 * KVBUF * (int)sizeof(uint32_t);  // 87040
    cudaFuncSetAttribute(attn_kernel, cudaFuncAttributeMaxDynamicSharedMemorySize,
                         attn_smem);
    attn_kernel<<<dim3(TT/64, BB*HH), 128, attn_smem>>>();

    // 3) output projection
    mma_gemm<1><<<dim3(CC/128, NTOK/128), 128, gemm_smem>>>(ao, wprojT, b_proj,
                                                            out, NTOK, CC, CC);
}